// round 10
// baseline (speedup 1.0000x reference)
#include <cuda_runtime.h>
#include <math.h>

#define NS 1024
#define HD 256
#define XD 128
#define S2 34   // k_pair smem row stride in float2 units (conflict-free LDS phases)

// scratch (device globals: no allocation allowed)
__device__ __align__(16) float g_xp[NS * HD];   // x @ Wx
__device__ __align__(16) float g_yp[NS * HD];   // y @ Wy + b1
__device__ double g_es;          // grand exp sum
__device__ double g_ds;          // diagonal sum
__device__ unsigned int g_cnt;   // tile-combine completion counter

typedef unsigned long long u64;

// split-K partials: [tile][half][acc][thread]  (thread-major -> coalesced)
__device__ __align__(16) u64 g_part[256][2][32][128];
__device__ unsigned int g_tcnt[256];   // per-tile arrival tickets (self-resetting)

__device__ __forceinline__ u64 pk2(float a, float b) {
    u64 r; asm("mov.b64 %0, {%1, %2};" : "=l"(r) : "f"(a), "f"(b)); return r;
}
__device__ __forceinline__ void up2(u64 v, float& a, float& b) {
    asm("mov.b64 {%0, %1}, %2;" : "=f"(a), "=f"(b) : "l"(v));
}
__device__ __forceinline__ u64 add2(u64 a, u64 b) {
    u64 r; asm("add.rn.f32x2 %0, %1, %2;" : "=l"(r) : "l"(a), "l"(b)); return r;
}
__device__ __forceinline__ u64 fma2(u64 a, u64 b, u64 c) {
    u64 r; asm("fma.rn.f32x2 %0, %1, %2, %3;" : "=l"(r) : "l"(a), "l"(b), "l"(c)); return r;
}

// acc += relu(xv + yv) * w, packed f32x2 (4 SASS instrs: ADD2, 2x FMAX, FFMA2)
__device__ __forceinline__ void step(u64 xv, u64 yv, u64 w, u64& acc) {
    asm("{\n\t"
        ".reg .f32 lo, hi;\n\t"
        ".reg .b64 s;\n\t"
        "add.rn.f32x2 s, %1, %2;\n\t"
        "mov.b64 {lo, hi}, s;\n\t"
        "max.f32 lo, lo, 0f00000000;\n\t"
        "max.f32 hi, hi, 0f00000000;\n\t"
        "mov.b64 s, {lo, hi};\n\t"
        "fma.rn.f32x2 %0, s, %3, %0;\n\t"
        "}" : "+l"(acc) : "l"(xv), "l"(yv), "l"(w));
}

// xp = x @ W1[:128]; yp = y @ W1[128:] + b1.
// 128 blocks (single wave) x 256 threads; 16 rows per block. (R7-proven)
__global__ void __launch_bounds__(256) k_gemm(
    const float* __restrict__ x, const float* __restrict__ y,
    const float* __restrict__ W1, const float* __restrict__ b1)
{
    if (blockIdx.x == 0 && threadIdx.x == 0) { g_es = 0.0; g_ds = 0.0; g_cnt = 0u; }

    __shared__ __align__(16) float xs[128 * 18];
    int b = blockIdx.x;
    int isY = b >> 6;
    int row0 = (b & 63) << 4;
    const float* src = isY ? y : x;
    const float* W = W1 + isY * (XD * HD);
    int t = threadIdx.x;

    #pragma unroll
    for (int p = 0; p < 8; p++) {
        int idx = t + p * 256;
        int r = idx >> 7, k = idx & 127;
        xs[k * 18 + r] = src[(row0 + r) * XD + k];
    }
    __syncthreads();

    u64 acc[8];
    #pragma unroll
    for (int m = 0; m < 8; m++) acc[m] = 0ull;

    #pragma unroll 8
    for (int k = 0; k < 128; k++) {
        float w = W[k * HD + t];
        u64 wd = pk2(w, w);
        #pragma unroll
        for (int m = 0; m < 8; m++)
            acc[m] = fma2(*(const u64*)&xs[k * 18 + 2 * m], wd, acc[m]);
    }

    float bias = isY ? b1[t] : 0.0f;
    float* dst = isY ? g_yp : g_xp;
    #pragma unroll
    for (int m = 0; m < 8; m++) {
        float v0, v1; up2(acc[m], v0, v1);
        dst[(row0 + 2 * m)     * HD + t] = v0 + bias;
        dst[(row0 + 2 * m + 1) * HD + t] = v1 + bias;
    }
}

// Pairwise kernel, split-K: grid (256 tiles, 2 K-halves), 128 threads, 4 CTAs/SM.
// Each CTA: 64x64 tile over 128 k (2 chunks). Thread = 8i x 4j x (2k packed).
// Halves combine via gmem partials; second finisher runs the exp epilogue.
__global__ void __launch_bounds__(128, 4) k_pair(
    const float* __restrict__ W2, const float* __restrict__ b2,
    float* __restrict__ out)
{
    __shared__ __align__(16) float2 xsh[64 * S2];   // j rows
    __shared__ __align__(16) float2 ysh[64 * S2];   // i rows
    __shared__ __align__(16) float2 wsh[128];
    __shared__ float rr[8];
    __shared__ int secondsh;

    int t = threadIdx.x;
    int tx = t & 15, ty = t >> 4;                   // tx: j base, ty: i base (0..7)
    int tile = blockIdx.x;                          // 0..255
    int half = blockIdx.y;                          // 0..1 (k 0..127 / 128..255)
    int jT = (tile & 15) << 6, iT = (tile >> 4) << 6;

    wsh[t] = ((const float2*)W2)[t];                // all 128 f2 of W2

    const float4* gx = (const float4*)g_xp;         // 64 f4 per 256-float row
    const float4* gy = (const float4*)g_yp;
    float4* xs4 = (float4*)xsh;                     // 17 f4 per row (= S2 f2)
    float4* ys4 = (float4*)ysh;

    u64 acc[32];
    #pragma unroll
    for (int p = 0; p < 32; p++) acc[p] = 0ull;

    #pragma unroll 1
    for (int c2 = 0; c2 < 2; c2++) {                // this half's 2 chunks
        int ch = half * 2 + c2;                     // global chunk 0..3
        __syncthreads();   // previous chunk reads done (and wsh visible on first pass)
        #pragma unroll
        for (int p = 0; p < 8; p++) {
            int idx = t + p * 128;                  // 0..1023
            int row = idx >> 4, c4 = idx & 15;
            xs4[row * 17 + c4] = gx[(jT + row) * 64 + ch * 16 + c4];
            ys4[row * 17 + c4] = gy[(iT + row) * 64 + ch * 16 + c4];
        }
        __syncthreads();

        #pragma unroll 8
        for (int k2 = 0; k2 < 32; k2++) {           // 2 k per iter
            u64 w = *(const u64*)&wsh[ch * 32 + k2];
            u64 xv[4];
            #pragma unroll
            for (int a = 0; a < 4; a++)
                xv[a] = *(const u64*)&xsh[(tx + 16 * a) * S2 + k2];
            u64 yv[8];
            #pragma unroll
            for (int b8 = 0; b8 < 8; b8++)
                yv[b8] = *(const u64*)&ysh[(ty + 8 * b8) * S2 + k2];
            #pragma unroll
            for (int b8 = 0; b8 < 8; b8++)
                #pragma unroll
                for (int a = 0; a < 4; a++)
                    step(xv[a], yv[b8], w, acc[b8 * 4 + a]);
        }
    }

    // ---- publish this half's partial dots ----
    #pragma unroll
    for (int p = 0; p < 32; p++)
        g_part[tile][half][p][t] = acc[p];
    __threadfence();
    __syncthreads();
    if (t == 0) {
        unsigned r = atomicAdd(&g_tcnt[tile], 1u);
        secondsh = (r == 1u) ? 1 : 0;
    }
    __syncthreads();
    if (!secondsh) return;                          // first finisher: done

    // ---- second finisher: combine + exp epilogue ----
    __threadfence();
    {
        const u64* other = &g_part[tile][1 - half][0][0];
        #pragma unroll
        for (int p = 0; p < 32; p++)
            acc[p] = add2(acc[p], other[p * 128 + t]);
    }

    float le = 0.0f, ld = 0.0f;
    #pragma unroll
    for (int b8 = 0; b8 < 8; b8++) {
        #pragma unroll
        for (int a = 0; a < 4; a++) {
            float lo, hi; up2(acc[b8 * 4 + a], lo, hi);
            float s = lo + hi;
            le += __expf(s);
            if (iT + ty + 8 * b8 == jT + tx + 16 * a) ld += s;
        }
    }

    #pragma unroll
    for (int o = 16; o > 0; o >>= 1) {
        le += __shfl_xor_sync(0xffffffffu, le, o);
        ld += __shfl_xor_sync(0xffffffffu, ld, o);
    }
    int wid = t >> 5, lane = t & 31;
    if (lane == 0) { rr[wid] = le; rr[4 + wid] = ld; }
    __syncthreads();
    if (t == 0) {
        float se = rr[0] + rr[1] + rr[2] + rr[3];
        float sd = rr[4] + rr[5] + rr[6] + rr[7];
        atomicAdd(&g_es, (double)se);
        if (iT == jT) atomicAdd(&g_ds, (double)sd);
        g_tcnt[tile] = 0u;                          // reset for next graph replay
        __threadfence();
        unsigned int c = atomicAdd(&g_cnt, 1u);
        if (c == 255u) {                            // all 256 tiles combined
            double es = atomicAdd(&g_es, 0.0);
            double ds = atomicAdd(&g_ds, 0.0);
            double bb = (double)b2[0];
            double lb = ds / (double)NS + bb
                      - exp(bb - 1.0) * es / ((double)NS * (double)NS);
            out[0] = (float)lb;
        }
    }
}

extern "C" void kernel_launch(void* const* d_in, const int* in_sizes, int n_in,
                              void* d_out, int out_size)
{
    (void)in_sizes; (void)n_in; (void)out_size;
    const float* x  = (const float*)d_in[0];
    const float* y  = (const float*)d_in[1];
    const float* W1 = (const float*)d_in[2];
    const float* b1 = (const float*)d_in[3];
    const float* W2 = (const float*)d_in[4];
    const float* b2 = (const float*)d_in[5];

    k_gemm<<<128, 256>>>(x, y, W1, b1);
    k_pair<<<dim3(256, 2), 128>>>(W2, b2, (float*)d_out);
}

// round 12
// speedup vs baseline: 1.2100x; 1.2100x over previous
#include <cuda_runtime.h>
#include <cuda_bf16.h>
#include <math.h>

#define NS 1024
#define HD 256
#define XD 128
#define SPW 17   // k_pair smem row stride in u32 (17r mod 32 distinct for r<16 -> conflict-free LDS.32)

// scratch (device globals: no allocation allowed)
__device__ __align__(16) unsigned int g_xb[NS * 128];  // bf16x2-packed x@Wx       [row][k2]
__device__ __align__(16) unsigned int g_yb[NS * 128];  // bf16x2-packed y@Wy + b1  [row][k2]
__device__ double g_es;          // grand exp sum
__device__ double g_ds;          // diagonal sum
__device__ unsigned int g_cnt;   // k_pair completion counter

typedef unsigned long long u64;
typedef unsigned int u32;

__device__ __forceinline__ u64 pk2(float a, float b) {
    u64 r; asm("mov.b64 %0, {%1, %2};" : "=l"(r) : "f"(a), "f"(b)); return r;
}
__device__ __forceinline__ void up2(u64 v, float& a, float& b) {
    asm("mov.b64 {%0, %1}, %2;" : "=f"(a), "=f"(b) : "l"(v));
}
__device__ __forceinline__ u64 fma2(u64 a, u64 b, u64 c) {
    u64 r; asm("fma.rn.f32x2 %0, %1, %2, %3;" : "=l"(r) : "l"(a), "l"(b), "l"(c)); return r;
}
// pack two f32 into bf16x2: hi half = hi, lo half = lo
__device__ __forceinline__ u32 cvt_bf2(float lo, float hi) {
    u32 r; asm("cvt.rn.bf16x2.f32 %0, %1, %2;" : "=r"(r) : "f"(hi), "f"(lo)); return r;
}

// bf16x2 lane-accumulate: acc2 += max(x2+y2, 0) * w2   (3 instrs, no unpack)
__device__ __forceinline__ void stepb(u32 x2, u32 y2, u32 w2, u32& acc) {
    asm("{\n\t"
        ".reg .b32 s;\n\t"
        "add.rn.bf16x2 s, %1, %2;\n\t"
        "max.bf16x2 s, s, %3;\n\t"
        "fma.rn.bf16x2 %0, s, %4, %0;\n\t"
        "}" : "+r"(acc) : "r"(x2), "r"(y2), "r"(0u), "r"(w2));
}

// drain bf16x2 lane-acc into f32 dot, reset acc
__device__ __forceinline__ void drain(u32& acc, float& dot) {
    float lo = __uint_as_float(acc << 16);
    float hi = __uint_as_float(acc & 0xFFFF0000u);
    dot += lo + hi;
    acc = 0u;
}

// Projections in fp32, outputs packed bf16x2 along k.
// 128 blocks (single wave) x 256 threads; 16 rows per block.
__global__ void __launch_bounds__(256) k_gemm(
    const float* __restrict__ x, const float* __restrict__ y,
    const float* __restrict__ W1, const float* __restrict__ b1)
{
    if (blockIdx.x == 0 && threadIdx.x == 0) { g_es = 0.0; g_ds = 0.0; g_cnt = 0u; }

    __shared__ __align__(16) float sbuf[16 * 258];   // phase A: xs[k*18+r]; phase B: stage[r*258+c]
    int b = blockIdx.x;
    int isY = b >> 6;
    int row0 = (b & 63) << 4;
    const float* src = isY ? y : x;
    const float* W = W1 + isY * (XD * HD);
    int t = threadIdx.x;

    #pragma unroll
    for (int p = 0; p < 8; p++) {
        int idx = t + p * 256;
        int r = idx >> 7, k = idx & 127;
        sbuf[k * 18 + r] = src[(row0 + r) * XD + k];
    }
    __syncthreads();

    u64 acc[8];
    #pragma unroll
    for (int m = 0; m < 8; m++) acc[m] = 0ull;

    #pragma unroll 8
    for (int k = 0; k < 128; k++) {
        float w = W[k * HD + t];
        u64 wd = pk2(w, w);
        #pragma unroll
        for (int m = 0; m < 8; m++)
            acc[m] = fma2(*(const u64*)&sbuf[k * 18 + 2 * m], wd, acc[m]);
    }
    __syncthreads();   // done reading xs; reuse sbuf as stage

    float bias = isY ? b1[t] : 0.0f;
    #pragma unroll
    for (int m = 0; m < 8; m++) {
        float v0, v1; up2(acc[m], v0, v1);
        sbuf[(2 * m)     * 258 + t] = v0 + bias;
        sbuf[(2 * m + 1) * 258 + t] = v1 + bias;
    }
    __syncthreads();

    // pack: thread -> column pair c2, half of the rows
    u32* dstb = isY ? g_yb : g_xb;
    int c2 = t & 127;
    int rh = (t >> 7) * 8;
    #pragma unroll
    for (int m = 0; m < 8; m++) {
        int r = rh + m;
        u32 p = cvt_bf2(sbuf[r * 258 + 2 * c2], sbuf[r * 258 + 2 * c2 + 1]);
        dstb[(row0 + r) * 128 + c2] = p;
    }
}

// Pairwise kernel: 32x32 tile per CTA, 128 threads, 8 CTAs/SM (1024 CTAs, balance ~1.01).
// Thread = 4i x 2j x (2k bf16-packed); 3-instr bf16 step; drain to f32 every 64 k.
__global__ void __launch_bounds__(128, 8) k_pair(
    const float* __restrict__ W2, const float* __restrict__ b2,
    float* __restrict__ out)
{
    __shared__ __align__(16) u32 xsh[32 * SPW];   // j rows, 16 u32 (32 k) per chunk
    __shared__ __align__(16) u32 ysh[32 * SPW];   // i rows
    __shared__ __align__(16) u32 wsh[128];        // W2 bf16x2, k-paired
    __shared__ float rr[8];

    int t = threadIdx.x;
    int tx = t & 15, ty = t >> 4;                 // j = tx, tx+16; i = ty + 8*b4
    int jT = blockIdx.x << 5, iT = blockIdx.y << 5;

    {
        float2 wv = ((const float2*)W2)[t];       // 128 threads cover all 128 pairs
        wsh[t] = cvt_bf2(wv.x, wv.y);
    }

    const float4* gx = (const float4*)g_xb;       // 32 f4 per row (128 u32)
    const float4* gy = (const float4*)g_yb;

    u32 accb[8];
    float dot[8];
    #pragma unroll
    for (int p = 0; p < 8; p++) { accb[p] = 0u; dot[p] = 0.0f; }

    #pragma unroll 1
    for (int ch = 0; ch < 8; ch++) {              // 32 k (16 u32) per chunk
        __syncthreads();   // previous chunk reads done (and wsh visible on first pass)
        // fill: 32 rows x 4 f4 per array; 1 f4 per thread per array
        {
            int row = t >> 2, c4 = t & 3;
            float4 vx = gx[(jT + row) * 32 + ch * 4 + c4];
            float4 vy = gy[(iT + row) * 32 + ch * 4 + c4];
            u32* xd = &xsh[row * SPW + 4 * c4];
            u32* yd = &ysh[row * SPW + 4 * c4];
            xd[0] = __float_as_uint(vx.x); xd[1] = __float_as_uint(vx.y);
            xd[2] = __float_as_uint(vx.z); xd[3] = __float_as_uint(vx.w);
            yd[0] = __float_as_uint(vy.x); yd[1] = __float_as_uint(vy.y);
            yd[2] = __float_as_uint(vy.z); yd[3] = __float_as_uint(vy.w);
        }
        __syncthreads();

        #pragma unroll
        for (int k2 = 0; k2 < 16; k2++) {         // 2 k per iter
            u32 w = wsh[ch * 16 + k2];
            u32 xv0 = xsh[tx * SPW + k2];
            u32 xv1 = xsh[(tx + 16) * SPW + k2];
            u32 yv[4];
            #pragma unroll
            for (int b4 = 0; b4 < 4; b4++)
                yv[b4] = ysh[(ty + 8 * b4) * SPW + k2];
            #pragma unroll
            for (int b4 = 0; b4 < 4; b4++) {
                stepb(xv0, yv[b4], w, accb[b4 * 2]);
                stepb(xv1, yv[b4], w, accb[b4 * 2 + 1]);
            }
        }

        if (ch & 1) {                             // drain every 64 k (32 HFMA2 per lane)
            #pragma unroll
            for (int p = 0; p < 8; p++) drain(accb[p], dot[p]);
        }
    }

    // epilogue: per-pair dot -> exp-sum + diagonal capture
    float le = 0.0f, ld = 0.0f;
    #pragma unroll
    for (int b4 = 0; b4 < 4; b4++) {
        #pragma unroll
        for (int a = 0; a < 2; a++) {
            float s = dot[b4 * 2 + a];
            le += __expf(s);
            if (iT + ty + 8 * b4 == jT + tx + 16 * a) ld += s;
        }
    }

    #pragma unroll
    for (int o = 16; o > 0; o >>= 1) {
        le += __shfl_xor_sync(0xffffffffu, le, o);
        ld += __shfl_xor_sync(0xffffffffu, ld, o);
    }
    int wid = t >> 5, lane = t & 31;
    if (lane == 0) { rr[wid] = le; rr[4 + wid] = ld; }
    __syncthreads();
    if (t == 0) {
        float se = rr[0] + rr[1] + rr[2] + rr[3];
        float sd = rr[4] + rr[5] + rr[6] + rr[7];
        atomicAdd(&g_es, (double)se);
        if (iT == jT) atomicAdd(&g_ds, (double)sd);
        __threadfence();
        unsigned int c = atomicAdd(&g_cnt, 1u);
        if (c == 1023u) {
            double es = atomicAdd(&g_es, 0.0);
            double ds = atomicAdd(&g_ds, 0.0);
            double bb = (double)b2[0];
            double lb = ds / (double)NS + bb
                      - exp(bb - 1.0) * es / ((double)NS * (double)NS);
            out[0] = (float)lb;
        }
    }
}

extern "C" void kernel_launch(void* const* d_in, const int* in_sizes, int n_in,
                              void* d_out, int out_size)
{
    (void)in_sizes; (void)n_in; (void)out_size;
    const float* x  = (const float*)d_in[0];
    const float* y  = (const float*)d_in[1];
    const float* W1 = (const float*)d_in[2];
    const float* b1 = (const float*)d_in[3];
    const float* W2 = (const float*)d_in[4];
    const float* b2 = (const float*)d_in[5];

    k_gemm<<<128, 256>>>(x, y, W1, b1);
    k_pair<<<dim3(32, 32), 128>>>(W2, b2, (float*)d_out);
}

// round 13
// speedup vs baseline: 1.2173x; 1.0060x over previous
#include <cuda_runtime.h>
#include <cuda_bf16.h>
#include <math.h>

#define NS 1024
#define HD 256
#define XD 128
#define SPW 17   // k_pair smem row stride in u32 (17r mod 32 distinct -> conflict-free LDS.32)

// scratch (device globals: no allocation allowed)
__device__ __align__(16) unsigned int g_xb[NS * 128];  // bf16x2-packed x@Wx       [row][k2]
__device__ __align__(16) unsigned int g_yb[NS * 128];  // bf16x2-packed y@Wy + b1  [row][k2]
__device__ double g_es;          // grand exp sum
__device__ double g_ds;          // diagonal sum
__device__ unsigned int g_cnt;   // k_pair completion counter

typedef unsigned long long u64;
typedef unsigned int u32;

__device__ __forceinline__ u64 pk2(float a, float b) {
    u64 r; asm("mov.b64 %0, {%1, %2};" : "=l"(r) : "f"(a), "f"(b)); return r;
}
__device__ __forceinline__ void up2(u64 v, float& a, float& b) {
    asm("mov.b64 {%0, %1}, %2;" : "=f"(a), "=f"(b) : "l"(v));
}
__device__ __forceinline__ u64 fma2(u64 a, u64 b, u64 c) {
    u64 r; asm("fma.rn.f32x2 %0, %1, %2, %3;" : "=l"(r) : "l"(a), "l"(b), "l"(c)); return r;
}
// pack two f32 into bf16x2: hi half = hi, lo half = lo
__device__ __forceinline__ u32 cvt_bf2(float lo, float hi) {
    u32 r; asm("cvt.rn.bf16x2.f32 %0, %1, %2;" : "=r"(r) : "f"(hi), "f"(lo)); return r;
}

// 2-instr step: acc2 += relu(x2 + y2) * w2   (relu fused into HFMA2 via x*1+y)
__device__ __forceinline__ void stepb(u32 x2, u32 y2, u32 w2, u32& acc) {
    asm("{\n\t"
        ".reg .b32 s;\n\t"
        "fma.rn.relu.bf16x2 s, %1, %2, %3;\n\t"
        "fma.rn.bf16x2 %0, s, %4, %0;\n\t"
        "}" : "+r"(acc) : "r"(x2), "r"(0x3F803F80u), "r"(y2), "r"(w2));
}

// drain bf16x2 lane-acc into f32 dot, reset acc
__device__ __forceinline__ void drain(u32& acc, float& dot) {
    float lo = __uint_as_float(acc << 16);
    float hi = __uint_as_float(acc & 0xFFFF0000u);
    dot += lo + hi;
    acc = 0u;
}

// Projections in fp32, outputs packed bf16x2 along k.
// 128 blocks (single wave) x 256 threads; 16 rows per block. (R12-proven)
__global__ void __launch_bounds__(256) k_gemm(
    const float* __restrict__ x, const float* __restrict__ y,
    const float* __restrict__ W1, const float* __restrict__ b1)
{
    if (blockIdx.x == 0 && threadIdx.x == 0) { g_es = 0.0; g_ds = 0.0; g_cnt = 0u; }

    __shared__ __align__(16) float sbuf[16 * 258];   // phase A: xs[k*18+r]; phase B: stage[r*258+c]
    int b = blockIdx.x;
    int isY = b >> 6;
    int row0 = (b & 63) << 4;
    const float* src = isY ? y : x;
    const float* W = W1 + isY * (XD * HD);
    int t = threadIdx.x;

    #pragma unroll
    for (int p = 0; p < 8; p++) {
        int idx = t + p * 256;
        int r = idx >> 7, k = idx & 127;
        sbuf[k * 18 + r] = src[(row0 + r) * XD + k];
    }
    __syncthreads();

    u64 acc[8];
    #pragma unroll
    for (int m = 0; m < 8; m++) acc[m] = 0ull;

    #pragma unroll 8
    for (int k = 0; k < 128; k++) {
        float w = W[k * HD + t];
        u64 wd = pk2(w, w);
        #pragma unroll
        for (int m = 0; m < 8; m++)
            acc[m] = fma2(*(const u64*)&sbuf[k * 18 + 2 * m], wd, acc[m]);
    }
    __syncthreads();   // done reading xs; reuse sbuf as stage

    float bias = isY ? b1[t] : 0.0f;
    #pragma unroll
    for (int m = 0; m < 8; m++) {
        float v0, v1; up2(acc[m], v0, v1);
        sbuf[(2 * m)     * 258 + t] = v0 + bias;
        sbuf[(2 * m + 1) * 258 + t] = v1 + bias;
    }
    __syncthreads();

    // pack: thread -> column pair c2, half of the rows
    u32* dstb = isY ? g_yb : g_xb;
    int c2 = t & 127;
    int rh = (t >> 7) * 8;
    #pragma unroll
    for (int m = 0; m < 8; m++) {
        int r = rh + m;
        u32 p = cvt_bf2(sbuf[r * 258 + 2 * c2], sbuf[r * 258 + 2 * c2 + 1]);
        dstb[(row0 + r) * 128 + c2] = p;
    }
}

// Pairwise kernel: 32x32 tile per CTA, **64 threads**, thread = 4i x 4j x (2k bf16).
// 1024 CTAs (~7/SM, balance 1.01); 2-instr fused-relu step; drain to f32 every 64 k.
__global__ void __launch_bounds__(64, 16) k_pair(
    const float* __restrict__ W2, const float* __restrict__ b2,
    float* __restrict__ out)
{
    __shared__ __align__(16) u32 xsh[32 * SPW];   // j rows, 16 u32 (32 k) per chunk
    __shared__ __align__(16) u32 ysh[32 * SPW];   // i rows
    __shared__ __align__(16) u32 wsh[128];        // W2 bf16x2, k-paired
    __shared__ float rr[4];

    int t = threadIdx.x;
    int tx = t & 7, ty = t >> 3;                  // j = tx + 8a; i = ty + 8b
    int jT = blockIdx.x << 5, iT = blockIdx.y << 5;

    {
        float2 w0 = ((const float2*)W2)[t];
        float2 w1 = ((const float2*)W2)[t + 64];
        wsh[t]      = cvt_bf2(w0.x, w0.y);
        wsh[t + 64] = cvt_bf2(w1.x, w1.y);
    }

    const float4* gx = (const float4*)g_xb;       // 32 f4 per row (128 u32)
    const float4* gy = (const float4*)g_yb;

    u32 accb[16];
    float dot[16];
    #pragma unroll
    for (int p = 0; p < 16; p++) { accb[p] = 0u; dot[p] = 0.0f; }

    #pragma unroll 1
    for (int ch = 0; ch < 8; ch++) {              // 32 k (16 u32) per chunk
        __syncthreads();   // previous chunk reads done (and wsh visible on first pass)
        // fill: 32 rows x 4 f4 per array = 128 f4; 2 per thread per array
        #pragma unroll
        for (int p = 0; p < 2; p++) {
            int idx = t + p * 64;                 // 0..127
            int row = idx >> 2, c4 = idx & 3;
            float4 vx = gx[(jT + row) * 32 + ch * 4 + c4];
            float4 vy = gy[(iT + row) * 32 + ch * 4 + c4];
            u32* xd = &xsh[row * SPW + 4 * c4];
            u32* yd = &ysh[row * SPW + 4 * c4];
            xd[0] = __float_as_uint(vx.x); xd[1] = __float_as_uint(vx.y);
            xd[2] = __float_as_uint(vx.z); xd[3] = __float_as_uint(vx.w);
            yd[0] = __float_as_uint(vy.x); yd[1] = __float_as_uint(vy.y);
            yd[2] = __float_as_uint(vy.z); yd[3] = __float_as_uint(vy.w);
        }
        __syncthreads();

        #pragma unroll
        for (int k2 = 0; k2 < 16; k2++) {         // 2 k per iter, 16 pairs per thread
            u32 w = wsh[ch * 16 + k2];
            u32 xv[4], yv[4];
            #pragma unroll
            for (int a = 0; a < 4; a++)
                xv[a] = xsh[(tx + 8 * a) * SPW + k2];
            #pragma unroll
            for (int b4 = 0; b4 < 4; b4++)
                yv[b4] = ysh[(ty + 8 * b4) * SPW + k2];
            #pragma unroll
            for (int b4 = 0; b4 < 4; b4++)
                #pragma unroll
                for (int a = 0; a < 4; a++)
                    stepb(xv[a], yv[b4], w, accb[b4 * 4 + a]);
        }

        if (ch & 1) {                             // drain every 64 k
            #pragma unroll
            for (int p = 0; p < 16; p++) drain(accb[p], dot[p]);
        }
    }

    // epilogue: per-pair dot -> exp-sum + diagonal capture
    float le = 0.0f, ld = 0.0f;
    #pragma unroll
    for (int b4 = 0; b4 < 4; b4++) {
        #pragma unroll
        for (int a = 0; a < 4; a++) {
            float s = dot[b4 * 4 + a];
            le += __expf(s);
            if (iT + ty + 8 * b4 == jT + tx + 8 * a) ld += s;
        }
    }

    #pragma unroll
    for (int o = 16; o > 0; o >>= 1) {
        le += __shfl_xor_sync(0xffffffffu, le, o);
        ld += __shfl_xor_sync(0xffffffffu, ld, o);
    }
    int wid = t >> 5, lane = t & 31;
    if (lane == 0) { rr[wid] = le; rr[2 + wid] = ld; }
    __syncthreads();
    if (t == 0) {
        float se = rr[0] + rr[1];
        float sd = rr[2] + rr[3];
        atomicAdd(&g_es, (double)se);
        if (iT == jT) atomicAdd(&g_ds, (double)sd);
        __threadfence();
        unsigned int c = atomicAdd(&g_cnt, 1u);
        if (c == 1023u) {
            double es = atomicAdd(&g_es, 0.0);
            double ds = atomicAdd(&g_ds, 0.0);
            double bb = (double)b2[0];
            double lb = ds / (double)NS + bb
                      - exp(bb - 1.0) * es / ((double)NS * (double)NS);
            out[0] = (float)lb;
        }
    }
}

extern "C" void kernel_launch(void* const* d_in, const int* in_sizes, int n_in,
                              void* d_out, int out_size)
{
    (void)in_sizes; (void)n_in; (void)out_size;
    const float* x  = (const float*)d_in[0];
    const float* y  = (const float*)d_in[1];
    const float* W1 = (const float*)d_in[2];
    const float* b1 = (const float*)d_in[3];
    const float* W2 = (const float*)d_in[4];
    const float* b2 = (const float*)d_in[5];

    k_gemm<<<128, 256>>>(x, y, W1, b1);
    k_pair<<<dim3(32, 32), 64>>>(W2, b2, (float*)d_out);
}

// round 14
// speedup vs baseline: 1.2808x; 1.0522x over previous
#include <cuda_runtime.h>
#include <cuda_bf16.h>
#include <math.h>

#define NS 1024
#define HD 256
#define XD 128
#define SPW 17   // k_pair smem row stride in u32 (17r mod 32 distinct -> conflict-free LDS.32)

// scratch (device globals: no allocation allowed)
__device__ __align__(16) unsigned int g_xb[NS * 128];  // bf16x2-packed x@Wx       [row][k2]
__device__ __align__(16) unsigned int g_yb[NS * 128];  // bf16x2-packed y@Wy + b1  [row][k2]
__device__ double g_es;          // grand exp sum
__device__ double g_ds;          // diagonal sum
__device__ unsigned int g_cnt;   // k_pair completion counter

typedef unsigned long long u64;
typedef unsigned int u32;

__device__ __forceinline__ u64 pk2(float a, float b) {
    u64 r; asm("mov.b64 %0, {%1, %2};" : "=l"(r) : "f"(a), "f"(b)); return r;
}
__device__ __forceinline__ void up2(u64 v, float& a, float& b) {
    asm("mov.b64 {%0, %1}, %2;" : "=f"(a), "=f"(b) : "l"(v));
}
__device__ __forceinline__ u64 fma2(u64 a, u64 b, u64 c) {
    u64 r; asm("fma.rn.f32x2 %0, %1, %2, %3;" : "=l"(r) : "l"(a), "l"(b), "l"(c)); return r;
}
// pack two f32 into bf16x2: hi half = hi, lo half = lo
__device__ __forceinline__ u32 cvt_bf2(float lo, float hi) {
    u32 r; asm("cvt.rn.bf16x2.f32 %0, %1, %2;" : "=r"(r) : "f"(hi), "f"(lo)); return r;
}

// 2-instr step: acc2 += relu(x2 + y2) * w2   (relu fused into HFMA2: relu(x*1+y))
__device__ __forceinline__ void stepb(u32 x2, u32 y2, u32 w2, u32& acc) {
    asm("{\n\t"
        ".reg .b32 s;\n\t"
        "fma.rn.relu.bf16x2 s, %1, %2, %3;\n\t"
        "fma.rn.bf16x2 %0, s, %4, %0;\n\t"
        "}" : "+r"(acc) : "r"(x2), "r"(0x3F803F80u), "r"(y2), "r"(w2));
}

// drain bf16x2 lane-acc into f32 dot, reset acc
__device__ __forceinline__ void drain(u32& acc, float& dot) {
    float lo = __uint_as_float(acc << 16);
    float hi = __uint_as_float(acc & 0xFFFF0000u);
    dot += lo + hi;
    acc = 0u;
}

// Projections in fp32, outputs packed bf16x2 along k.
// 128 blocks (single wave) x 256 threads; 16 rows per block. (R12-proven)
__global__ void __launch_bounds__(256) k_gemm(
    const float* __restrict__ x, const float* __restrict__ y,
    const float* __restrict__ W1, const float* __restrict__ b1)
{
    if (blockIdx.x == 0 && threadIdx.x == 0) { g_es = 0.0; g_ds = 0.0; g_cnt = 0u; }

    __shared__ __align__(16) float sbuf[16 * 258];   // phase A: xs[k*18+r]; phase B: stage[r*258+c]
    int b = blockIdx.x;
    int isY = b >> 6;
    int row0 = (b & 63) << 4;
    const float* src = isY ? y : x;
    const float* W = W1 + isY * (XD * HD);
    int t = threadIdx.x;

    #pragma unroll
    for (int p = 0; p < 8; p++) {
        int idx = t + p * 256;
        int r = idx >> 7, k = idx & 127;
        sbuf[k * 18 + r] = src[(row0 + r) * XD + k];
    }
    __syncthreads();

    u64 acc[8];
    #pragma unroll
    for (int m = 0; m < 8; m++) acc[m] = 0ull;

    #pragma unroll 8
    for (int k = 0; k < 128; k++) {
        float w = W[k * HD + t];
        u64 wd = pk2(w, w);
        #pragma unroll
        for (int m = 0; m < 8; m++)
            acc[m] = fma2(*(const u64*)&sbuf[k * 18 + 2 * m], wd, acc[m]);
    }
    __syncthreads();   // done reading xs; reuse sbuf as stage

    float bias = isY ? b1[t] : 0.0f;
    #pragma unroll
    for (int m = 0; m < 8; m++) {
        float v0, v1; up2(acc[m], v0, v1);
        sbuf[(2 * m)     * 258 + t] = v0 + bias;
        sbuf[(2 * m + 1) * 258 + t] = v1 + bias;
    }
    __syncthreads();

    // pack: thread -> column pair c2, half of the rows
    u32* dstb = isY ? g_yb : g_xb;
    int c2 = t & 127;
    int rh = (t >> 7) * 8;
    #pragma unroll
    for (int m = 0; m < 8; m++) {
        int r = rh + m;
        u32 p = cvt_bf2(sbuf[r * 258 + 2 * c2], sbuf[r * 258 + 2 * c2 + 1]);
        dstb[(row0 + r) * 128 + c2] = p;
    }
}

// Pairwise kernel: 32x32 tile per CTA, 128 threads, 8 CTAs/SM (1024 CTAs, balance ~1.01).
// Thread = 4i x 2j x (2k bf16-packed); 2-instr fused-relu step; drain to f32 every 64 k.
// (R12-proven shape; only the inner step changed.)
__global__ void __launch_bounds__(128, 8) k_pair(
    const float* __restrict__ W2, const float* __restrict__ b2,
    float* __restrict__ out)
{
    __shared__ __align__(16) u32 xsh[32 * SPW];   // j rows, 16 u32 (32 k) per chunk
    __shared__ __align__(16) u32 ysh[32 * SPW];   // i rows
    __shared__ __align__(16) u32 wsh[128];        // W2 bf16x2, k-paired
    __shared__ float rr[8];

    int t = threadIdx.x;
    int tx = t & 15, ty = t >> 4;                 // j = tx, tx+16; i = ty + 8*b4
    int jT = blockIdx.x << 5, iT = blockIdx.y << 5;

    {
        float2 wv = ((const float2*)W2)[t];       // 128 threads cover all 128 pairs
        wsh[t] = cvt_bf2(wv.x, wv.y);
    }

    const float4* gx = (const float4*)g_xb;       // 32 f4 per row (128 u32)
    const float4* gy = (const float4*)g_yb;

    u32 accb[8];
    float dot[8];
    #pragma unroll
    for (int p = 0; p < 8; p++) { accb[p] = 0u; dot[p] = 0.0f; }

    #pragma unroll 1
    for (int ch = 0; ch < 8; ch++) {              // 32 k (16 u32) per chunk
        __syncthreads();   // previous chunk reads done (and wsh visible on first pass)
        // fill: 32 rows x 4 f4 per array; 1 f4 per thread per array
        {
            int row = t >> 2, c4 = t & 3;
            float4 vx = gx[(jT + row) * 32 + ch * 4 + c4];
            float4 vy = gy[(iT + row) * 32 + ch * 4 + c4];
            u32* xd = &xsh[row * SPW + 4 * c4];
            u32* yd = &ysh[row * SPW + 4 * c4];
            xd[0] = __float_as_uint(vx.x); xd[1] = __float_as_uint(vx.y);
            xd[2] = __float_as_uint(vx.z); xd[3] = __float_as_uint(vx.w);
            yd[0] = __float_as_uint(vy.x); yd[1] = __float_as_uint(vy.y);
            yd[2] = __float_as_uint(vy.z); yd[3] = __float_as_uint(vy.w);
        }
        __syncthreads();

        #pragma unroll
        for (int k2 = 0; k2 < 16; k2++) {         // 2 k per iter
            u32 w = wsh[ch * 16 + k2];
            u32 xv0 = xsh[tx * SPW + k2];
            u32 xv1 = xsh[(tx + 16) * SPW + k2];
            u32 yv[4];
            #pragma unroll
            for (int b4 = 0; b4 < 4; b4++)
                yv[b4] = ysh[(ty + 8 * b4) * SPW + k2];
            #pragma unroll
            for (int b4 = 0; b4 < 4; b4++) {
                stepb(xv0, yv[b4], w, accb[b4 * 2]);
                stepb(xv1, yv[b4], w, accb[b4 * 2 + 1]);
            }
        }

        if (ch & 1) {                             // drain every 64 k
            #pragma unroll
            for (int p = 0; p < 8; p++) drain(accb[p], dot[p]);
        }
    }

    // epilogue: per-pair dot -> exp-sum + diagonal capture
    float le = 0.0f, ld = 0.0f;
    #pragma unroll
    for (int b4 = 0; b4 < 4; b4++) {
        #pragma unroll
        for (int a = 0; a < 2; a++) {
            float s = dot[b4 * 2 + a];
            le += __expf(s);
            if (iT + ty + 8 * b4 == jT + tx + 16 * a) ld += s;
        }
    }

    #pragma unroll
    for (int o = 16; o > 0; o >>= 1) {
        le += __shfl_xor_sync(0xffffffffu, le, o);
        ld += __shfl_xor_sync(0xffffffffu, ld, o);
    }
    int wid = t >> 5, lane = t & 31;
    if (lane == 0) { rr[wid] = le; rr[4 + wid] = ld; }
    __syncthreads();
    if (t == 0) {
        float se = rr[0] + rr[1] + rr[2] + rr[3];
        float sd = rr[4] + rr[5] + rr[6] + rr[7];
        atomicAdd(&g_es, (double)se);
        if (iT == jT) atomicAdd(&g_ds, (double)sd);
        __threadfence();
        unsigned int c = atomicAdd(&g_cnt, 1u);
        if (c == 1023u) {
            double es = atomicAdd(&g_es, 0.0);
            double ds = atomicAdd(&g_ds, 0.0);
            double bb = (double)b2[0];
            double lb = ds / (double)NS + bb
                      - exp(bb - 1.0) * es / ((double)NS * (double)NS);
            out[0] = (float)lb;
        }
    }
}

extern "C" void kernel_launch(void* const* d_in, const int* in_sizes, int n_in,
                              void* d_out, int out_size)
{
    (void)in_sizes; (void)n_in; (void)out_size;
    const float* x  = (const float*)d_in[0];
    const float* y  = (const float*)d_in[1];
    const float* W1 = (const float*)d_in[2];
    const float* b1 = (const float*)d_in[3];
    const float* W2 = (const float*)d_in[4];
    const float* b2 = (const float*)d_in[5];

    k_gemm<<<128, 256>>>(x, y, W1, b1);
    k_pair<<<dim3(32, 32), 128>>>(W2, b2, (float*)d_out);
}

// round 15
// speedup vs baseline: 1.3043x; 1.0183x over previous
#include <cuda_runtime.h>
#include <cuda_bf16.h>
#include <math.h>

#define NS 1024
#define HD 256
#define XD 128
#define SPW 18   // k_pair smem row stride in u32 (18r mod 32 distinct for r<16 -> conflict-free LDS.64)

// scratch (device globals: no allocation allowed)
__device__ __align__(16) unsigned int g_xb[NS * 128];  // bf16x2-packed x@Wx       [row][k2]
__device__ __align__(16) unsigned int g_yb[NS * 128];  // bf16x2-packed y@Wy + b1  [row][k2]
__device__ double g_es;          // grand exp sum
__device__ double g_ds;          // diagonal sum
__device__ unsigned int g_cnt;   // k_pair completion counter

typedef unsigned long long u64;
typedef unsigned int u32;

__device__ __forceinline__ u64 pk2(float a, float b) {
    u64 r; asm("mov.b64 %0, {%1, %2};" : "=l"(r) : "f"(a), "f"(b)); return r;
}
__device__ __forceinline__ void up2(u64 v, float& a, float& b) {
    asm("mov.b64 {%0, %1}, %2;" : "=f"(a), "=f"(b) : "l"(v));
}
__device__ __forceinline__ u64 fma2(u64 a, u64 b, u64 c) {
    u64 r; asm("fma.rn.f32x2 %0, %1, %2, %3;" : "=l"(r) : "l"(a), "l"(b), "l"(c)); return r;
}
// pack two f32 into bf16x2: hi half = hi, lo half = lo
__device__ __forceinline__ u32 cvt_bf2(float lo, float hi) {
    u32 r; asm("cvt.rn.bf16x2.f32 %0, %1, %2;" : "=r"(r) : "f"(hi), "f"(lo)); return r;
}

// 2-instr step: acc2 += relu(x2 + y2) * w2   (relu fused into HFMA2: relu(x*1+y))
__device__ __forceinline__ void stepb(u32 x2, u32 y2, u32 w2, u32& acc) {
    asm("{\n\t"
        ".reg .b32 s;\n\t"
        "fma.rn.relu.bf16x2 s, %1, %2, %3;\n\t"
        "fma.rn.bf16x2 %0, s, %4, %0;\n\t"
        "}" : "+r"(acc) : "r"(x2), "r"(0x3F803F80u), "r"(y2), "r"(w2));
}

// drain bf16x2 lane-acc into f32 dot, reset acc
__device__ __forceinline__ void drain(u32& acc, float& dot) {
    float lo = __uint_as_float(acc << 16);
    float hi = __uint_as_float(acc & 0xFFFF0000u);
    dot += lo + hi;
    acc = 0u;
}

// Projections in fp32, outputs packed bf16x2 along k.
// 128 blocks (single wave) x 256 threads; 16 rows per block. (R12-proven)
__global__ void __launch_bounds__(256) k_gemm(
    const float* __restrict__ x, const float* __restrict__ y,
    const float* __restrict__ W1, const float* __restrict__ b1)
{
    if (blockIdx.x == 0 && threadIdx.x == 0) { g_es = 0.0; g_ds = 0.0; g_cnt = 0u; }

    __shared__ __align__(16) float sbuf[16 * 258];   // phase A: xs[k*18+r]; phase B: stage[r*258+c]
    int b = blockIdx.x;
    int isY = b >> 6;
    int row0 = (b & 63) << 4;
    const float* src = isY ? y : x;
    const float* W = W1 + isY * (XD * HD);
    int t = threadIdx.x;

    #pragma unroll
    for (int p = 0; p < 8; p++) {
        int idx = t + p * 256;
        int r = idx >> 7, k = idx & 127;
        sbuf[k * 18 + r] = src[(row0 + r) * XD + k];
    }
    __syncthreads();

    u64 acc[8];
    #pragma unroll
    for (int m = 0; m < 8; m++) acc[m] = 0ull;

    #pragma unroll 8
    for (int k = 0; k < 128; k++) {
        float w = W[k * HD + t];
        u64 wd = pk2(w, w);
        #pragma unroll
        for (int m = 0; m < 8; m++)
            acc[m] = fma2(*(const u64*)&sbuf[k * 18 + 2 * m], wd, acc[m]);
    }
    __syncthreads();   // done reading xs; reuse sbuf as stage

    float bias = isY ? b1[t] : 0.0f;
    #pragma unroll
    for (int m = 0; m < 8; m++) {
        float v0, v1; up2(acc[m], v0, v1);
        sbuf[(2 * m)     * 258 + t] = v0 + bias;
        sbuf[(2 * m + 1) * 258 + t] = v1 + bias;
    }
    __syncthreads();

    // pack: thread -> column pair c2, half of the rows
    u32* dstb = isY ? g_yb : g_xb;
    int c2 = t & 127;
    int rh = (t >> 7) * 8;
    #pragma unroll
    for (int m = 0; m < 8; m++) {
        int r = rh + m;
        u32 p = cvt_bf2(sbuf[r * 258 + 2 * c2], sbuf[r * 258 + 2 * c2 + 1]);
        dstb[(row0 + r) * 128 + c2] = p;
    }
}

// Pairwise kernel: 32x32 tile per CTA, 128 threads, 7 CTAs/SM (1024 CTAs, balance ~1.01).
// Thread = 4i x 2j x (4k per iter via LDS.64); 2-instr fused-relu step; drain every 64 k.
__global__ void __launch_bounds__(128, 7) k_pair(
    const float* __restrict__ W2, const float* __restrict__ b2,
    float* __restrict__ out)
{
    __shared__ __align__(16) u32 xsh[32 * SPW];   // j rows, 16 u32 (32 k) per chunk
    __shared__ __align__(16) u32 ysh[32 * SPW];   // i rows
    __shared__ __align__(16) u32 wsh[128];        // W2 bf16x2, k-paired
    __shared__ float rr[8];

    int t = threadIdx.x;
    int tx = t & 15, ty = t >> 4;                 // j = tx, tx+16; i = ty + 8*b4
    int jT = blockIdx.x << 5, iT = blockIdx.y << 5;

    {
        float2 wv = ((const float2*)W2)[t];       // 128 threads cover all 128 pairs
        wsh[t] = cvt_bf2(wv.x, wv.y);
    }

    const float4* gx = (const float4*)g_xb;       // 32 f4 per row (128 u32)
    const float4* gy = (const float4*)g_yb;

    u32 accb[8];
    float dot[8];
    #pragma unroll
    for (int p = 0; p < 8; p++) { accb[p] = 0u; dot[p] = 0.0f; }

    #pragma unroll 1
    for (int ch = 0; ch < 8; ch++) {              // 32 k (16 u32) per chunk
        __syncthreads();   // previous chunk reads done (and wsh visible on first pass)
        // fill: 32 rows x 4 f4 per array; 1 f4 per thread per array (stored as 2x u64)
        {
            int row = t >> 2, c4 = t & 3;
            float4 vx = gx[(jT + row) * 32 + ch * 4 + c4];
            float4 vy = gy[(iT + row) * 32 + ch * 4 + c4];
            u64* xd = (u64*)&xsh[row * SPW + 4 * c4];
            u64* yd = (u64*)&ysh[row * SPW + 4 * c4];
            xd[0] = pk2(vx.x, vx.y);
            xd[1] = pk2(vx.z, vx.w);
            yd[0] = pk2(vy.x, vy.y);
            yd[1] = pk2(vy.z, vy.w);
        }
        __syncthreads();

        #pragma unroll
        for (int k4 = 0; k4 < 8; k4++) {          // 4 k per iter (one u64 = two bf16x2)
            u64 w = *(const u64*)&wsh[ch * 16 + 2 * k4];
            u32 wlo = (u32)w, whi = (u32)(w >> 32);
            u64 xv0 = *(const u64*)&xsh[tx * SPW + 2 * k4];
            u64 xv1 = *(const u64*)&xsh[(tx + 16) * SPW + 2 * k4];
            u32 x0l = (u32)xv0, x0h = (u32)(xv0 >> 32);
            u32 x1l = (u32)xv1, x1h = (u32)(xv1 >> 32);
            u64 yv[4];
            #pragma unroll
            for (int b4 = 0; b4 < 4; b4++)
                yv[b4] = *(const u64*)&ysh[(ty + 8 * b4) * SPW + 2 * k4];
            #pragma unroll
            for (int b4 = 0; b4 < 4; b4++) {
                u32 yl = (u32)yv[b4], yh = (u32)(yv[b4] >> 32);
                stepb(x0l, yl, wlo, accb[b4 * 2]);
                stepb(x0h, yh, whi, accb[b4 * 2]);
                stepb(x1l, yl, wlo, accb[b4 * 2 + 1]);
                stepb(x1h, yh, whi, accb[b4 * 2 + 1]);
            }
        }

        if (ch & 1) {                             // drain every 64 k
            #pragma unroll
            for (int p = 0; p < 8; p++) drain(accb[p], dot[p]);
        }
    }

    // epilogue: per-pair dot -> exp-sum + diagonal capture
    float le = 0.0f, ld = 0.0f;
    #pragma unroll
    for (int b4 = 0; b4 < 4; b4++) {
        #pragma unroll
        for (int a = 0; a < 2; a++) {
            float s = dot[b4 * 2 + a];
            le += __expf(s);
            if (iT + ty + 8 * b4 == jT + tx + 16 * a) ld += s;
        }
    }

    #pragma unroll
    for (int o = 16; o > 0; o >>= 1) {
        le += __shfl_xor_sync(0xffffffffu, le, o);
        ld += __shfl_xor_sync(0xffffffffu, ld, o);
    }
    int wid = t >> 5, lane = t & 31;
    if (lane == 0) { rr[wid] = le; rr[4 + wid] = ld; }
    __syncthreads();
    if (t == 0) {
        float se = rr[0] + rr[1] + rr[2] + rr[3];
        float sd = rr[4] + rr[5] + rr[6] + rr[7];
        atomicAdd(&g_es, (double)se);
        if (iT == jT) atomicAdd(&g_ds, (double)sd);
        __threadfence();
        unsigned int c = atomicAdd(&g_cnt, 1u);
        if (c == 1023u) {
            double es = atomicAdd(&g_es, 0.0);
            double ds = atomicAdd(&g_ds, 0.0);
            double bb = (double)b2[0];
            double lb = ds / (double)NS + bb
                      - exp(bb - 1.0) * es / ((double)NS * (double)NS);
            out[0] = (float)lb;
        }
    }
}

extern "C" void kernel_launch(void* const* d_in, const int* in_sizes, int n_in,
                              void* d_out, int out_size)
{
    (void)in_sizes; (void)n_in; (void)out_size;
    const float* x  = (const float*)d_in[0];
    const float* y  = (const float*)d_in[1];
    const float* W1 = (const float*)d_in[2];
    const float* b1 = (const float*)d_in[3];
    const float* W2 = (const float*)d_in[4];
    const float* b2 = (const float*)d_in[5];

    k_gemm<<<128, 256>>>(x, y, W1, b1);
    k_pair<<<dim3(32, 32), 128>>>(W2, b2, (float*)d_out);
}

// round 17
// speedup vs baseline: 1.3683x; 1.0490x over previous
#include <cuda_runtime.h>
#include <cuda_bf16.h>
#include <math.h>

#define NS 1024
#define HD 256
#define XD 128
#define SPW 66   // k_pair smem row stride in u32 (= 33 u64; 33r mod 16 distinct -> conflict-free LDS.64)

// scratch (device globals: no allocation allowed)
__device__ __align__(16) unsigned int g_xb[NS * 128];  // bf16x2-packed x@Wx       [row][k2]
__device__ __align__(16) unsigned int g_yb[NS * 128];  // bf16x2-packed y@Wy + b1  [row][k2]
__device__ double g_es;          // grand exp sum
__device__ double g_ds;          // diagonal sum
__device__ unsigned int g_cnt;   // k_pair completion counter

typedef unsigned long long u64;
typedef unsigned int u32;

__device__ __forceinline__ u64 pk2(float a, float b) {
    u64 r; asm("mov.b64 %0, {%1, %2};" : "=l"(r) : "f"(a), "f"(b)); return r;
}
__device__ __forceinline__ void up2(u64 v, float& a, float& b) {
    asm("mov.b64 {%0, %1}, %2;" : "=f"(a), "=f"(b) : "l"(v));
}
__device__ __forceinline__ u64 fma2(u64 a, u64 b, u64 c) {
    u64 r; asm("fma.rn.f32x2 %0, %1, %2, %3;" : "=l"(r) : "l"(a), "l"(b), "l"(c)); return r;
}
// pack two f32 into bf16x2: hi half = hi, lo half = lo
__device__ __forceinline__ u32 cvt_bf2(float lo, float hi) {
    u32 r; asm("cvt.rn.bf16x2.f32 %0, %1, %2;" : "=r"(r) : "f"(hi), "f"(lo)); return r;
}

// 2-instr step: acc2 += relu(x2 + y2) * w2   (relu fused into HFMA2: relu(x*1+y))
__device__ __forceinline__ void stepb(u32 x2, u32 y2, u32 w2, u32& acc) {
    asm("{\n\t"
        ".reg .b32 s;\n\t"
        "fma.rn.relu.bf16x2 s, %1, %2, %3;\n\t"
        "fma.rn.bf16x2 %0, s, %4, %0;\n\t"
        "}" : "+r"(acc) : "r"(x2), "r"(0x3F803F80u), "r"(y2), "r"(w2));
}

// drain bf16x2 lane-acc into f32 dot, reset acc
__device__ __forceinline__ void drain(u32& acc, float& dot) {
    float lo = __uint_as_float(acc << 16);
    float hi = __uint_as_float(acc & 0xFFFF0000u);
    dot += lo + hi;
    acc = 0u;
}

// Projections in fp32, outputs packed bf16x2 along k.
// 128 blocks (single wave) x 256 threads; 16 rows per block. (R12-proven)
__global__ void __launch_bounds__(256) k_gemm(
    const float* __restrict__ x, const float* __restrict__ y,
    const float* __restrict__ W1, const float* __restrict__ b1)
{
    if (blockIdx.x == 0 && threadIdx.x == 0) { g_es = 0.0; g_ds = 0.0; g_cnt = 0u; }

    __shared__ __align__(16) float sbuf[16 * 258];   // phase A: xs[k*18+r]; phase B: stage[r*258+c]
    int b = blockIdx.x;
    int isY = b >> 6;
    int row0 = (b & 63) << 4;
    const float* src = isY ? y : x;
    const float* W = W1 + isY * (XD * HD);
    int t = threadIdx.x;

    #pragma unroll
    for (int p = 0; p < 8; p++) {
        int idx = t + p * 256;
        int r = idx >> 7, k = idx & 127;
        sbuf[k * 18 + r] = src[(row0 + r) * XD + k];
    }
    __syncthreads();

    u64 acc[8];
    #pragma unroll
    for (int m = 0; m < 8; m++) acc[m] = 0ull;

    #pragma unroll 8
    for (int k = 0; k < 128; k++) {
        float w = W[k * HD + t];
        u64 wd = pk2(w, w);
        #pragma unroll
        for (int m = 0; m < 8; m++)
            acc[m] = fma2(*(const u64*)&sbuf[k * 18 + 2 * m], wd, acc[m]);
    }
    __syncthreads();   // done reading xs; reuse sbuf as stage

    float bias = isY ? b1[t] : 0.0f;
    #pragma unroll
    for (int m = 0; m < 8; m++) {
        float v0, v1; up2(acc[m], v0, v1);
        sbuf[(2 * m)     * 258 + t] = v0 + bias;
        sbuf[(2 * m + 1) * 258 + t] = v1 + bias;
    }
    __syncthreads();

    // pack: thread -> column pair c2, half of the rows
    u32* dstb = isY ? g_yb : g_xb;
    int c2 = t & 127;
    int rh = (t >> 7) * 8;
    #pragma unroll
    for (int m = 0; m < 8; m++) {
        int r = rh + m;
        u32 p = cvt_bf2(sbuf[r * 258 + 2 * c2], sbuf[r * 258 + 2 * c2 + 1]);
        dstb[(row0 + r) * 128 + c2] = p;
    }
}

// Pairwise kernel: 32x32 tile per CTA, 128 threads, 7 CTAs/SM (1024 CTAs).
// 2 chunks of 128 k (4 syncs, 2 LDG fills); 4 k per iter via LDS.64;
// de-chained lo/hi passes; drain every 64 k (mid-chunk + end-of-chunk).
__global__ void __launch_bounds__(128, 7) k_pair(
    const float* __restrict__ W2, const float* __restrict__ b2,
    float* __restrict__ out)
{
    __shared__ __align__(16) u32 xsh[32 * SPW];   // j rows, 64 u32 (128 k) per chunk
    __shared__ __align__(16) u32 ysh[32 * SPW];   // i rows
    __shared__ __align__(16) u32 wsh[128];        // W2 bf16x2, k-paired
    __shared__ float rr[8];

    int t = threadIdx.x;
    int tx = t & 15, ty = t >> 4;                 // j = tx, tx+16; i = ty + 8*b4
    int jT = blockIdx.x << 5, iT = blockIdx.y << 5;

    {
        float2 wv = ((const float2*)W2)[t];       // 128 threads cover all 128 pairs
        wsh[t] = cvt_bf2(wv.x, wv.y);
    }

    const float4* gx = (const float4*)g_xb;       // 32 f4 per row (128 u32)
    const float4* gy = (const float4*)g_yb;

    u32 accb[8];
    float dot[8];
    #pragma unroll
    for (int p = 0; p < 8; p++) { accb[p] = 0u; dot[p] = 0.0f; }

    #pragma unroll 1
    for (int ch = 0; ch < 2; ch++) {              // 128 k (64 u32) per chunk
        __syncthreads();   // previous chunk reads done (and wsh visible on first pass)
        // fill: 32 rows x 16 f4 per array = 512 f4/array; 4 per thread per array
        #pragma unroll
        for (int p = 0; p < 4; p++) {
            int idx = t + p * 128;                // 0..511
            int row = idx >> 4, c4 = idx & 15;
            float4 vx = gx[(jT + row) * 32 + ch * 16 + c4];
            float4 vy = gy[(iT + row) * 32 + ch * 16 + c4];
            u64* xd = (u64*)&xsh[row * SPW + 4 * c4];
            u64* yd = (u64*)&ysh[row * SPW + 4 * c4];
            xd[0] = pk2(vx.x, vx.y);
            xd[1] = pk2(vx.z, vx.w);
            yd[0] = pk2(vy.x, vy.y);
            yd[1] = pk2(vy.z, vy.w);
        }
        __syncthreads();

        #pragma unroll 1
        for (int half = 0; half < 2; half++) {    // 64 k per half, drain after each
            #pragma unroll 8
            for (int k4 = 0; k4 < 16; k4++) {     // 4 k per iter (one u64 = two bf16x2)
                int kk = half * 16 + k4;          // u64 index within chunk: 0..31
                u64 w = *(const u64*)&wsh[ch * 64 + 2 * kk];
                u32 wlo = (u32)w, whi = (u32)(w >> 32);
                u64 xv0 = *(const u64*)&xsh[tx * SPW + 2 * kk];
                u64 xv1 = *(const u64*)&xsh[(tx + 16) * SPW + 2 * kk];
                u32 x0l = (u32)xv0, x0h = (u32)(xv0 >> 32);
                u32 x1l = (u32)xv1, x1h = (u32)(xv1 >> 32);
                u64 yv[4];
                #pragma unroll
                for (int b4 = 0; b4 < 4; b4++)
                    yv[b4] = *(const u64*)&ysh[(ty + 8 * b4) * SPW + 2 * kk];
                // lo pass: 8 independent acc updates
                #pragma unroll
                for (int b4 = 0; b4 < 4; b4++) {
                    u32 yl = (u32)yv[b4];
                    stepb(x0l, yl, wlo, accb[b4 * 2]);
                    stepb(x1l, yl, wlo, accb[b4 * 2 + 1]);
                }
                // hi pass: same accs, 16 instrs after their last update
                #pragma unroll
                for (int b4 = 0; b4 < 4; b4++) {
                    u32 yh = (u32)(yv[b4] >> 32);
                    stepb(x0h, yh, whi, accb[b4 * 2]);
                    stepb(x1h, yh, whi, accb[b4 * 2 + 1]);
                }
            }
            // drain every 64 k (same cadence as R15)
            #pragma unroll
            for (int p = 0; p < 8; p++) drain(accb[p], dot[p]);
        }
    }

    // epilogue: per-pair dot -> exp-sum + diagonal capture
    float le = 0.0f, ld = 0.0f;
    #pragma unroll
    for (int b4 = 0; b4 < 4; b4++) {
        #pragma unroll
        for (int a = 0; a < 2; a++) {
            float s = dot[b4 * 2 + a];
            le += __expf(s);
            if (iT + ty + 8 * b4 == jT + tx + 16 * a) ld += s;
        }
    }

    #pragma unroll
    for (int o = 16; o > 0; o >>= 1) {
        le += __shfl_xor_sync(0xffffffffu, le, o);
        ld += __shfl_xor_sync(0xffffffffu, ld, o);
    }
    int wid = t >> 5, lane = t & 31;
    if (lane == 0) { rr[wid] = le; rr[4 + wid] = ld; }
    __syncthreads();
    if (t == 0) {
        float se = rr[0] + rr[1] + rr[2] + rr[3];
        float sd = rr[4] + rr[5] + rr[6] + rr[7];
        atomicAdd(&g_es, (double)se);
        if (iT == jT) atomicAdd(&g_ds, (double)sd);
        __threadfence();
        unsigned int c = atomicAdd(&g_cnt, 1u);
        if (c == 1023u) {
            double es = atomicAdd(&g_es, 0.0);
            double ds = atomicAdd(&g_ds, 0.0);
            double bb = (double)b2[0];
            double lb = ds / (double)NS + bb
                      - exp(bb - 1.0) * es / ((double)NS * (double)NS);
            out[0] = (float)lb;
        }
    }
}

extern "C" void kernel_launch(void* const* d_in, const int* in_sizes, int n_in,
                              void* d_out, int out_size)
{
    (void)in_sizes; (void)n_in; (void)out_size;
    const float* x  = (const float*)d_in[0];
    const float* y  = (const float*)d_in[1];
    const float* W1 = (const float*)d_in[2];
    const float* b1 = (const float*)d_in[3];
    const float* W2 = (const float*)d_in[4];
    const float* b2 = (const float*)d_in[5];

    k_gemm<<<128, 256>>>(x, y, W1, b1);
    k_pair<<<dim3(32, 32), 128>>>(W2, b2, (float*)d_out);
}